// round 3
// baseline (speedup 1.0000x reference)
#include <cuda_runtime.h>
#include <cstddef>
#include <cstdint>

// ---------------------------------------------------------------------------
// Problem constants (shapes fixed by the dataset)
// ---------------------------------------------------------------------------
#define NN 50000
#define EE 800000

// ---------------------------------------------------------------------------
// Device-global scratch (no dynamic allocation allowed)
// ---------------------------------------------------------------------------
__device__ float g_bufA[(size_t)NN * 256];
__device__ float g_bufB[(size_t)NN * 256];
__device__ float g_bufC[(size_t)NN * 256];
__device__ float g_b64A[(size_t)NN * 64];
__device__ float g_b64B[(size_t)NN * 64];
__device__ float g_b64C[(size_t)NN * 64];
__device__ float g_b16A[(size_t)NN * 16];
__device__ float g_b16B[(size_t)NN * 16];
__device__ float g_b16C[(size_t)NN * 16];
__device__ float g_als[(size_t)NN * 4];
__device__ float g_ald[(size_t)NN * 4];
__device__ float g_dinv[NN];
__device__ int   g_deg[NN];
__device__ int   g_cur[NN];
__device__ int   g_rowptr[NN + 1];
__device__ int   g_csr[EE];
__device__ float g_s1[256], g_q1[256];
__device__ float g_s2[64],  g_q2[64];
__device__ float g_s3[16],  g_q3[16];
__device__ float g_scale[256], g_shift[256];
__device__ int   g_is64;

__device__ __forceinline__ float lk01(float x) { return x > 0.f ? x : 0.01f * x; }
__device__ __forceinline__ float lk2 (float x) { return x > 0.f ? x : 0.2f  * x; }

// ---------------------------------------------------------------------------
// Edge dtype detection (int64 vs int32 delivery)
// ---------------------------------------------------------------------------
__global__ void k_detect(const int* __restrict__ ei32, int E) {
    __shared__ int acc[32];
    int t = threadIdx.x;
    int o = 0;
    for (int i = 0; i < 8; i++) {
        int idx = 2 * (t + i * 32) + 1;
        if (idx < 2 * E) o |= ei32[idx];
    }
    acc[t] = o;
    __syncthreads();
    if (t == 0) {
        int r = 0;
        for (int i = 0; i < 32; i++) r |= acc[i];
        g_is64 = (r == 0) ? 1 : 0;
    }
}

__device__ __forceinline__ int edge_src(const void* ei, int E, int e) {
    if (g_is64) return (int)((const long long*)ei)[e];
    return ((const int*)ei)[e];
}
__device__ __forceinline__ int edge_dst(const void* ei, int E, int e) {
    if (g_is64) return (int)((const long long*)ei)[(size_t)E + e];
    return ((const int*)ei)[(size_t)E + e];
}

// ---------------------------------------------------------------------------
// Graph preprocessing
// ---------------------------------------------------------------------------
__global__ void k_zero(int n) {
    int i = blockIdx.x * blockDim.x + threadIdx.x;
    if (i < n)   { g_deg[i] = 0; g_cur[i] = 0; }
    if (i < 256) { g_s1[i] = 0.f; g_q1[i] = 0.f; }
    if (i < 64)  { g_s2[i] = 0.f; g_q2[i] = 0.f; }
    if (i < 16)  { g_s3[i] = 0.f; g_q3[i] = 0.f; }
}

__global__ void k_count(const void* __restrict__ ei, int E, int n) {
    int e = blockIdx.x * blockDim.x + threadIdx.x;
    if (e >= E) return;
    int d = edge_dst(ei, E, e);
    if ((unsigned)d < (unsigned)n) atomicAdd(&g_deg[d], 1);
}

__global__ void k_dinv(int n) {
    int i = blockIdx.x * blockDim.x + threadIdx.x;
    if (i < n) g_dinv[i] = rsqrtf((float)g_deg[i] + 1.0f);
}

__global__ void k_scan(int n) {
    __shared__ int sh[1024];
    int t = threadIdx.x;
    int chunk = (n + 1023) / 1024;
    int b = t * chunk;
    int e = b + chunk; if (e > n) e = n;
    int sum = 0;
    for (int i = b; i < e; i++) sum += g_deg[i];
    sh[t] = sum;
    __syncthreads();
    for (int off = 1; off < 1024; off <<= 1) {
        int v = (t >= off) ? sh[t - off] : 0;
        __syncthreads();
        sh[t] += v;
        __syncthreads();
    }
    int excl = (t == 0) ? 0 : sh[t - 1];
    for (int i = b; i < e; i++) { g_rowptr[i] = excl; excl += g_deg[i]; }
    if (t == 1023) g_rowptr[n] = sh[1023];
}

__global__ void k_fill(const void* __restrict__ ei, int E, int n) {
    int e = blockIdx.x * blockDim.x + threadIdx.x;
    if (e >= E) return;
    int src = edge_src(ei, E, e);
    int dst = edge_dst(ei, E, e);
    if ((unsigned)src >= (unsigned)n || (unsigned)dst >= (unsigned)n) return;
    int pos = g_rowptr[dst] + atomicAdd(&g_cur[dst], 1);
    if ((unsigned)pos < (unsigned)EE) g_csr[pos] = src;
}

// ---------------------------------------------------------------------------
// Tensor-core tf32 GEMM with 3-term compensation (fp32-class accuracy).
// C[M,Nc] = A[M,K] @ B[K,Nc] (+bias). Tile 128x128, kchunk 32, 256 threads.
// Requires K % 32 == 0, Nc % 8 == 0.
// smem (dynamic, 64KB): fragment-ordered Ahi/Alo [4kt][8mt][32lane][4reg],
//                       Bhi/Blo [4kt][16nt][32lane][2reg]
// ---------------------------------------------------------------------------
__device__ __forceinline__ uint32_t f2tf32(float x) {
    uint32_t r;
    asm("cvt.rna.tf32.f32 %0, %1;" : "=r"(r) : "f"(x));
    return r;
}

__device__ __forceinline__ void mma_tf32(float* c, const uint32_t* a, const uint32_t* b) {
    asm volatile(
        "mma.sync.aligned.m16n8k8.row.col.f32.tf32.tf32.f32 "
        "{%0,%1,%2,%3}, {%4,%5,%6,%7}, {%8,%9}, {%0,%1,%2,%3};"
        : "+f"(c[0]), "+f"(c[1]), "+f"(c[2]), "+f"(c[3])
        : "r"(a[0]), "r"(a[1]), "r"(a[2]), "r"(a[3]), "r"(b[0]), "r"(b[1]));
}

__global__ void __launch_bounds__(256) k_gemm_tf32(
    const float* __restrict__ A, const float* __restrict__ B,
    const float* __restrict__ bias, float* __restrict__ C,
    int M, int K, int Nc)
{
    extern __shared__ uint32_t sm[];
    uint32_t* sAhi = sm;
    uint32_t* sAlo = sm + 4096;
    uint32_t* sBhi = sm + 8192;
    uint32_t* sBlo = sm + 12288;

    int tid = threadIdx.x;
    int lane = tid & 31, warp = tid >> 5;
    int wm = warp >> 2, wn = warp & 3;          // 2 x 4 warp grid
    int row0 = blockIdx.y * 128, col0 = blockIdx.x * 128;

    float acc[4][4][4];
#pragma unroll
    for (int mt = 0; mt < 4; mt++)
#pragma unroll
        for (int nt = 0; nt < 4; nt++)
#pragma unroll
            for (int r = 0; r < 4; r++) acc[mt][nt][r] = 0.f;

    float4 aR[4], bR[4];

    auto loadg = [&](int kbase) {
#pragma unroll
        for (int i = 0; i < 4; i++) {
            int idx = tid + i * 256;
            int r = idx >> 3, kc = (idx & 7) * 4;     // A: [128 rows][8 float4]
            int gr = row0 + r;
            if (gr < M) aR[i] = *(const float4*)(A + (size_t)gr * K + kbase + kc);
            else        aR[i] = make_float4(0.f, 0.f, 0.f, 0.f);
            int bk = idx >> 5, nc = (idx & 31) * 4;   // B: [32 k][32 float4]
            int gc = col0 + nc;
            if (gc + 3 < Nc) bR[i] = *(const float4*)(B + (size_t)(kbase + bk) * Nc + gc);
            else             bR[i] = make_float4(0.f, 0.f, 0.f, 0.f);
        }
    };

    auto store_s = [&]() {
#pragma unroll
        for (int i = 0; i < 4; i++) {
            int idx = tid + i * 256;
            // --- A ---
            int r = idx >> 3, kc = (idx & 7) * 4;
            int ktile = kc >> 3, mtile = r >> 4;
            int regb = (((r & 15) >= 8) ? 1 : 0) + (((kc & 7) >= 4) ? 2 : 0);
            int lb = (r & 7) * 4;
            float va[4] = {aR[i].x, aR[i].y, aR[i].z, aR[i].w};
#pragma unroll
            for (int c = 0; c < 4; c++) {
                uint32_t hi = f2tf32(va[c]);
                uint32_t lo = f2tf32(va[c] - __uint_as_float(hi));
                int o = ((ktile * 8 + mtile) * 32 + lb + c) * 4 + regb;
                sAhi[o] = hi; sAlo[o] = lo;
            }
            // --- B ---
            int bk = idx >> 5, nc = (idx & 31) * 4;
            int bkt = bk >> 3;
            int regB = ((bk & 7) >= 4) ? 1 : 0;
            float vb[4] = {bR[i].x, bR[i].y, bR[i].z, bR[i].w};
#pragma unroll
            for (int c = 0; c < 4; c++) {
                int nidx = nc + c;
                int ntile = nidx >> 3;
                int ln = (nidx & 7) * 4 + (bk & 3);
                uint32_t hi = f2tf32(vb[c]);
                uint32_t lo = f2tf32(vb[c] - __uint_as_float(hi));
                int o = ((bkt * 16 + ntile) * 32 + ln) * 2 + regB;
                sBhi[o] = hi; sBlo[o] = lo;
            }
        }
    };

    int nch = K >> 5;
    loadg(0);
    store_s();
    __syncthreads();

    for (int ch = 1; ch <= nch; ch++) {
        if (ch < nch) loadg(ch * 32);
#pragma unroll
        for (int kt = 0; kt < 4; kt++) {
            uint4 ah[4], al[4];
            uint2 bh[4], bl[4];
#pragma unroll
            for (int mt = 0; mt < 4; mt++) {
                int o = ((kt * 8 + wm * 4 + mt) * 32 + lane) * 4;
                ah[mt] = *(const uint4*)&sAhi[o];
                al[mt] = *(const uint4*)&sAlo[o];
            }
#pragma unroll
            for (int nt = 0; nt < 4; nt++) {
                int o = ((kt * 16 + wn * 4 + nt) * 32 + lane) * 2;
                bh[nt] = *(const uint2*)&sBhi[o];
                bl[nt] = *(const uint2*)&sBlo[o];
            }
#pragma unroll
            for (int mt = 0; mt < 4; mt++) {
#pragma unroll
                for (int nt = 0; nt < 4; nt++) {
                    mma_tf32(acc[mt][nt], (const uint32_t*)&ah[mt], (const uint32_t*)&bh[nt]);
                    mma_tf32(acc[mt][nt], (const uint32_t*)&al[mt], (const uint32_t*)&bh[nt]);
                    mma_tf32(acc[mt][nt], (const uint32_t*)&ah[mt], (const uint32_t*)&bl[nt]);
                }
            }
        }
        __syncthreads();
        if (ch < nch) { store_s(); __syncthreads(); }
    }

    // epilogue
    int gid = lane >> 2, tig = lane & 3;
#pragma unroll
    for (int mt = 0; mt < 4; mt++) {
#pragma unroll
        for (int nt = 0; nt < 4; nt++) {
            int col = col0 + wn * 32 + nt * 8 + tig * 2;
            if (col < Nc) {
                float b0 = bias ? bias[col] : 0.f;
                float b1 = bias ? bias[col + 1] : 0.f;
                int r1 = row0 + wm * 64 + mt * 16 + gid;
                if (r1 < M) {
                    float2 o = make_float2(acc[mt][nt][0] + b0, acc[mt][nt][1] + b1);
                    *(float2*)(C + (size_t)r1 * Nc + col) = o;
                }
                int r2 = r1 + 8;
                if (r2 < M) {
                    float2 o = make_float2(acc[mt][nt][2] + b0, acc[mt][nt][3] + b1);
                    *(float2*)(C + (size_t)r2 * Nc + col) = o;
                }
            }
        }
    }
}

// ---------------------------------------------------------------------------
// SIMT SGEMM (for small layer-3/4 GEMMs). 128x128 tile, 8x8 micro, BK=8.
// ---------------------------------------------------------------------------
__global__ void __launch_bounds__(256) k_gemm(
    const float* __restrict__ A, const float* __restrict__ B,
    const float* __restrict__ bias, float* __restrict__ C,
    int M, int K, int Nc)
{
    __shared__ float As[8][132];
    __shared__ float Bs[8][128];
    int tid = threadIdx.x;
    int tx = tid & 15, ty = tid >> 4;
    int row0 = blockIdx.y * 128, col0 = blockIdx.x * 128;

    int arow = tid >> 1;
    int ak   = (tid & 1) * 4;
    int brow = tid >> 5;
    int bc   = (tid & 31) * 4;

    bool aok = (row0 + arow) < M;
    bool bok = (col0 + bc + 3) < Nc;

    float acc[8][8];
#pragma unroll
    for (int i = 0; i < 8; i++)
#pragma unroll
        for (int j = 0; j < 8; j++) acc[i][j] = 0.f;

    for (int k0 = 0; k0 < K; k0 += 8) {
        float4 av = make_float4(0.f, 0.f, 0.f, 0.f);
        if (aok) av = *(const float4*)(A + (size_t)(row0 + arow) * K + k0 + ak);
        As[ak + 0][arow] = av.x;
        As[ak + 1][arow] = av.y;
        As[ak + 2][arow] = av.z;
        As[ak + 3][arow] = av.w;
        float4 bv = make_float4(0.f, 0.f, 0.f, 0.f);
        if (bok) bv = *(const float4*)(B + (size_t)(k0 + brow) * Nc + col0 + bc);
        *(float4*)&Bs[brow][bc] = bv;
        __syncthreads();
#pragma unroll
        for (int k = 0; k < 8; k++) {
            float4 a0 = *(const float4*)&As[k][ty * 8];
            float4 a1 = *(const float4*)&As[k][ty * 8 + 4];
            float4 b0 = *(const float4*)&Bs[k][tx * 8];
            float4 b1 = *(const float4*)&Bs[k][tx * 8 + 4];
            float a[8] = {a0.x, a0.y, a0.z, a0.w, a1.x, a1.y, a1.z, a1.w};
            float b[8] = {b0.x, b0.y, b0.z, b0.w, b1.x, b1.y, b1.z, b1.w};
#pragma unroll
            for (int i = 0; i < 8; i++)
#pragma unroll
                for (int j = 0; j < 8; j++) acc[i][j] += a[i] * b[j];
        }
        __syncthreads();
    }

    bool cok = (col0 + tx * 8 + 7) < Nc;
    float bvv[8];
#pragma unroll
    for (int j = 0; j < 8; j++)
        bvv[j] = (bias && cok) ? bias[col0 + tx * 8 + j] : 0.f;

    if (cok) {
#pragma unroll
        for (int i = 0; i < 8; i++) {
            int r = row0 + ty * 8 + i;
            if (r < M) {
                float* cp = C + (size_t)r * Nc + col0 + tx * 8;
                float4 o0 = make_float4(acc[i][0] + bvv[0], acc[i][1] + bvv[1],
                                        acc[i][2] + bvv[2], acc[i][3] + bvv[3]);
                float4 o1 = make_float4(acc[i][4] + bvv[4], acc[i][5] + bvv[5],
                                        acc[i][6] + bvv[6], acc[i][7] + bvv[7]);
                *(float4*)cp = o0;
                *(float4*)(cp + 4) = o1;
            }
        }
    }
}

// ---------------------------------------------------------------------------
// GCN gather kernels
// ---------------------------------------------------------------------------
__global__ void k_gcn_gather256(const float* __restrict__ h, const float* __restrict__ bias,
                                float* __restrict__ out, int n)
{
    int gt = blockIdx.x * blockDim.x + threadIdx.x;
    int nd = gt >> 5, lane = gt & 31;
    if (nd >= n) return;
    int f0 = lane * 8;
    float din = g_dinv[nd];
    float sw = din * din;
    const float4* hp = (const float4*)(h + (size_t)nd * 256 + f0);
    float4 v0 = hp[0], v1 = hp[1];
    const float4* bp = (const float4*)(bias + f0);
    float4 b0 = bp[0], b1 = bp[1];
    float4 a0, a1;
    a0.x = v0.x * sw + b0.x; a0.y = v0.y * sw + b0.y;
    a0.z = v0.z * sw + b0.z; a0.w = v0.w * sw + b0.w;
    a1.x = v1.x * sw + b1.x; a1.y = v1.y * sw + b1.y;
    a1.z = v1.z * sw + b1.z; a1.w = v1.w * sw + b1.w;
    int e = g_rowptr[nd], end = g_rowptr[nd + 1];
    for (; e < end; e++) {
        int s = g_csr[e];
        float wg = g_dinv[s] * din;
        const float4* sp = (const float4*)(h + (size_t)s * 256 + f0);
        float4 u0 = sp[0], u1 = sp[1];
        a0.x += wg * u0.x; a0.y += wg * u0.y; a0.z += wg * u0.z; a0.w += wg * u0.w;
        a1.x += wg * u1.x; a1.y += wg * u1.y; a1.z += wg * u1.z; a1.w += wg * u1.w;
    }
    float4* op = (float4*)(out + (size_t)nd * 256 + f0);
    op[0] = a0; op[1] = a1;
}

template <int C>
__global__ void k_gcn_gather(const float* __restrict__ h, const float* __restrict__ bias,
                             float* __restrict__ out, int n)
{
    const int G = C / 4;
    int gt = blockIdx.x * blockDim.x + threadIdx.x;
    int nd = gt / G, sub = gt % G;
    if (nd >= n) return;
    int f0 = sub * 4;
    float din = g_dinv[nd];
    float sw = din * din;
    float4 v = *(const float4*)(h + (size_t)nd * C + f0);
    float4 b = *(const float4*)(bias + f0);
    float4 a;
    a.x = v.x * sw + b.x; a.y = v.y * sw + b.y;
    a.z = v.z * sw + b.z; a.w = v.w * sw + b.w;
    int e = g_rowptr[nd], end = g_rowptr[nd + 1];
    for (; e < end; e++) {
        int s = g_csr[e];
        float wg = g_dinv[s] * din;
        float4 u = *(const float4*)(h + (size_t)s * C + f0);
        a.x += wg * u.x; a.y += wg * u.y; a.z += wg * u.z; a.w += wg * u.w;
    }
    *(float4*)(out + (size_t)nd * C + f0) = a;
}

// ---------------------------------------------------------------------------
// GAT kernels
// ---------------------------------------------------------------------------
__global__ void k_al(const float* __restrict__ hg, const float* __restrict__ a_s,
                     const float* __restrict__ a_d, int n)
{
    int gt = blockIdx.x * blockDim.x + threadIdx.x;
    int w = gt >> 5, lane = gt & 31;
    if (w >= n) return;
    float s0 = 0.f, s1 = 0.f, s2 = 0.f, s3 = 0.f;
    float d0 = 0.f, d1 = 0.f, d2 = 0.f, d3 = 0.f;
#pragma unroll
    for (int j = 0; j < 2; j++) {
        int f = lane * 4 + j * 128;
        float4 v  = *(const float4*)(hg + (size_t)w * 256 + f);
        float4 as = *(const float4*)(a_s + f);
        float4 ad = *(const float4*)(a_d + f);
        float ps = v.x * as.x + v.y * as.y + v.z * as.z + v.w * as.w;
        float pd = v.x * ad.x + v.y * ad.y + v.z * ad.z + v.w * ad.w;
        bool hi = (lane & 16) != 0;
        if (j == 0) { if (hi) { s1 += ps; d1 += pd; } else { s0 += ps; d0 += pd; } }
        else        { if (hi) { s3 += ps; d3 += pd; } else { s2 += ps; d2 += pd; } }
    }
#pragma unroll
    for (int off = 16; off >= 1; off >>= 1) {
        s0 += __shfl_xor_sync(0xffffffffu, s0, off);
        s1 += __shfl_xor_sync(0xffffffffu, s1, off);
        s2 += __shfl_xor_sync(0xffffffffu, s2, off);
        s3 += __shfl_xor_sync(0xffffffffu, s3, off);
        d0 += __shfl_xor_sync(0xffffffffu, d0, off);
        d1 += __shfl_xor_sync(0xffffffffu, d1, off);
        d2 += __shfl_xor_sync(0xffffffffu, d2, off);
        d3 += __shfl_xor_sync(0xffffffffu, d3, off);
    }
    if (lane == 0) {
        *(float4*)(g_als + 4 * (size_t)w) = make_float4(s0, s1, s2, s3);
        *(float4*)(g_ald + 4 * (size_t)w) = make_float4(d0, d1, d2, d3);
    }
}

__global__ void k_gat(const float* __restrict__ hg, const float* __restrict__ bg,
                      float* __restrict__ out, int n)
{
    int gt = blockIdx.x * blockDim.x + threadIdx.x;
    int w = gt >> 5, lane = gt & 31;
    if (w >= n) return;
    float4 ad = *(const float4*)(g_ald + 4 * (size_t)w);
    float4 sf = *(const float4*)(g_als + 4 * (size_t)w);
    float e0 = lk2(sf.x + ad.x), e1 = lk2(sf.y + ad.y);
    float e2 = lk2(sf.z + ad.z), e3 = lk2(sf.w + ad.w);
    float m0 = e0, m1 = e1, m2 = e2, m3 = e3;
    int beg = g_rowptr[w], end = g_rowptr[w + 1];
    for (int e = beg; e < end; e++) {
        int s = g_csr[e];
        float4 a = *(const float4*)(g_als + 4 * (size_t)s);
        m0 = fmaxf(m0, lk2(a.x + ad.x));
        m1 = fmaxf(m1, lk2(a.y + ad.y));
        m2 = fmaxf(m2, lk2(a.z + ad.z));
        m3 = fmaxf(m3, lk2(a.w + ad.w));
    }
    float den0 = __expf(e0 - m0), den1 = __expf(e1 - m1);
    float den2 = __expf(e2 - m2), den3 = __expf(e3 - m3);
    int f0 = lane * 8;
    int head = lane >> 3;
    float wself = head == 0 ? den0 : head == 1 ? den1 : head == 2 ? den2 : den3;
    const float4* hp = (const float4*)(hg + (size_t)w * 256 + f0);
    float4 v0 = hp[0], v1 = hp[1];
    float a0 = wself * v0.x, a1 = wself * v0.y, a2 = wself * v0.z, a3 = wself * v0.w;
    float a4 = wself * v1.x, a5 = wself * v1.y, a6 = wself * v1.z, a7 = wself * v1.w;
    for (int e = beg; e < end; e++) {
        int s = g_csr[e];
        float4 a = *(const float4*)(g_als + 4 * (size_t)s);
        float w0 = __expf(lk2(a.x + ad.x) - m0);
        float w1 = __expf(lk2(a.y + ad.y) - m1);
        float w2 = __expf(lk2(a.z + ad.z) - m2);
        float w3 = __expf(lk2(a.w + ad.w) - m3);
        den0 += w0; den1 += w1; den2 += w2; den3 += w3;
        float ws = head == 0 ? w0 : head == 1 ? w1 : head == 2 ? w2 : w3;
        const float4* sp = (const float4*)(hg + (size_t)s * 256 + f0);
        float4 u0 = sp[0], u1 = sp[1];
        a0 += ws * u0.x; a1 += ws * u0.y; a2 += ws * u0.z; a3 += ws * u0.w;
        a4 += ws * u1.x; a5 += ws * u1.y; a6 += ws * u1.z; a7 += ws * u1.w;
    }
    float dsel = head == 0 ? den0 : head == 1 ? den1 : head == 2 ? den2 : den3;
    float sc = 0.25f / dsel;
    a0 *= sc; a1 *= sc; a2 *= sc; a3 *= sc;
    a4 *= sc; a5 *= sc; a6 *= sc; a7 *= sc;
    a0 += __shfl_xor_sync(0xffffffffu, a0, 8);  a0 += __shfl_xor_sync(0xffffffffu, a0, 16);
    a1 += __shfl_xor_sync(0xffffffffu, a1, 8);  a1 += __shfl_xor_sync(0xffffffffu, a1, 16);
    a2 += __shfl_xor_sync(0xffffffffu, a2, 8);  a2 += __shfl_xor_sync(0xffffffffu, a2, 16);
    a3 += __shfl_xor_sync(0xffffffffu, a3, 8);  a3 += __shfl_xor_sync(0xffffffffu, a3, 16);
    a4 += __shfl_xor_sync(0xffffffffu, a4, 8);  a4 += __shfl_xor_sync(0xffffffffu, a4, 16);
    a5 += __shfl_xor_sync(0xffffffffu, a5, 8);  a5 += __shfl_xor_sync(0xffffffffu, a5, 16);
    a6 += __shfl_xor_sync(0xffffffffu, a6, 8);  a6 += __shfl_xor_sync(0xffffffffu, a6, 16);
    a7 += __shfl_xor_sync(0xffffffffu, a7, 8);  a7 += __shfl_xor_sync(0xffffffffu, a7, 16);
    if (lane < 8) {
        const float4* bp = (const float4*)(bg + lane * 8);
        float4 b0 = bp[0], b1 = bp[1];
        float4 o0 = make_float4(a0 + b0.x, a1 + b0.y, a2 + b0.z, a3 + b0.w);
        float4 o1 = make_float4(a4 + b1.x, a5 + b1.y, a6 + b1.z, a7 + b1.w);
        float4* op = (float4*)(out + (size_t)w * 64 + lane * 8);
        op[0] = o0; op[1] = o1;
    }
}

// ---------------------------------------------------------------------------
// BatchNorm: stats / finalize / apply(+leaky+residual)
// ---------------------------------------------------------------------------
template <int C>
__global__ void k_bnstats(const float* __restrict__ x, float* __restrict__ gsum,
                          float* __restrict__ gsq, int n)
{
    __shared__ float ss[256], qq[256];
    int tid = threadIdx.x;
    const int R = 256 / C;
    int c = tid % C, r0 = tid / C;
    float s = 0.f, q = 0.f;
    for (int r = blockIdx.x * R + r0; r < n; r += gridDim.x * R) {
        float v = x[(size_t)r * C + c];
        s += v; q += v * v;
    }
    ss[tid] = s; qq[tid] = q;
    __syncthreads();
#pragma unroll
    for (int off = 128; off >= C; off >>= 1) {
        if (tid < off) { ss[tid] += ss[tid + off]; qq[tid] += qq[tid + off]; }
        __syncthreads();
    }
    if (tid < C) {
        atomicAdd(&gsum[tid], ss[tid]);
        atomicAdd(&gsq[tid],  qq[tid]);
    }
}

template <int C>
__global__ void k_bnfin(const float* __restrict__ gsum, const float* __restrict__ gsq,
                        const float* __restrict__ g, const float* __restrict__ be, int n)
{
    int c = threadIdx.x;
    if (c >= C) return;
    float inv = 1.0f / (float)n;
    float mu = gsum[c] * inv;
    float var = gsq[c] * inv - mu * mu;
    float sc = g[c] * rsqrtf(var + 1e-5f);
    g_scale[c] = sc;
    g_shift[c] = be[c] - mu * sc;
}

template <int C>
__global__ void k_apply(const float* __restrict__ x, const float* __restrict__ res,
                        float* __restrict__ out, int n)
{
    int i = blockIdx.x * blockDim.x + threadIdx.x;
    int total = n * (C / 4);
    if (i >= total) return;
    int c4 = i % (C / 4);
    float4 sc = *(const float4*)(g_scale + c4 * 4);
    float4 sh = *(const float4*)(g_shift + c4 * 4);
    float4 v = ((const float4*)x)[i];
    float4 r = ((const float4*)res)[i];
    float4 o;
    o.x = lk01(v.x * sc.x + sh.x) + r.x;
    o.y = lk01(v.y * sc.y + sh.y) + r.y;
    o.z = lk01(v.z * sc.z + sh.z) + r.z;
    o.w = lk01(v.w * sc.w + sh.w) + r.w;
    ((float4*)out)[i] = o;
}

// ---------------------------------------------------------------------------
// Launcher
// ---------------------------------------------------------------------------
extern "C" void kernel_launch(void* const* d_in, const int* in_sizes, int n_in,
                              void* d_out, int out_size)
{
    const float* x     = (const float*)d_in[0];
    const void*  ei    = d_in[1];
    const float* W1    = (const float*)d_in[2];
    const float* b1    = (const float*)d_in[3];
    const float* g1    = (const float*)d_in[4];
    const float* be1   = (const float*)d_in[5];
    const float* Wg    = (const float*)d_in[6];
    const float* a_src = (const float*)d_in[7];
    const float* a_dst = (const float*)d_in[8];
    const float* bg    = (const float*)d_in[9];
    const float* g2    = (const float*)d_in[10];
    const float* be2   = (const float*)d_in[11];
    const float* W3    = (const float*)d_in[12];
    const float* b3    = (const float*)d_in[13];
    const float* g3    = (const float*)d_in[14];
    const float* be3   = (const float*)d_in[15];
    const float* W4    = (const float*)d_in[16];
    const float* b4    = (const float*)d_in[17];
    const float* r1W   = (const float*)d_in[18];
    const float* r1b   = (const float*)d_in[19];
    const float* r2W   = (const float*)d_in[20];
    const float* r2b   = (const float*)d_in[21];
    const float* r3W   = (const float*)d_in[22];
    const float* r3b   = (const float*)d_in[23];
    const float* pW    = (const float*)d_in[24];
    const float* pb    = (const float*)d_in[25];

    int n = in_sizes[0] / 256;
    int E = in_sizes[1] / 2;
    if (E > EE) E = EE;

    float *pA, *pB, *pC, *p64A, *p64B, *p64C, *p16A, *p16B, *p16C;
    float *ps1, *pq1, *ps2, *pq2, *ps3, *pq3;
    cudaGetSymbolAddress((void**)&pA,   g_bufA);
    cudaGetSymbolAddress((void**)&pB,   g_bufB);
    cudaGetSymbolAddress((void**)&pC,   g_bufC);
    cudaGetSymbolAddress((void**)&p64A, g_b64A);
    cudaGetSymbolAddress((void**)&p64B, g_b64B);
    cudaGetSymbolAddress((void**)&p64C, g_b64C);
    cudaGetSymbolAddress((void**)&p16A, g_b16A);
    cudaGetSymbolAddress((void**)&p16B, g_b16B);
    cudaGetSymbolAddress((void**)&p16C, g_b16C);
    cudaGetSymbolAddress((void**)&ps1, g_s1);
    cudaGetSymbolAddress((void**)&pq1, g_q1);
    cudaGetSymbolAddress((void**)&ps2, g_s2);
    cudaGetSymbolAddress((void**)&pq2, g_q2);
    cudaGetSymbolAddress((void**)&ps3, g_s3);
    cudaGetSymbolAddress((void**)&pq3, g_q3);

    float* outp = (float*)d_out;

    static bool attr_set = false;
    if (!attr_set) {
        cudaFuncSetAttribute(k_gemm_tf32, cudaFuncAttributeMaxDynamicSharedMemorySize, 65536);
        attr_set = true;
    }

    // --- graph preprocessing: CSR by dst ---
    k_detect<<<1, 32>>>((const int*)ei, E);
    k_zero  <<<(n + 255) / 256, 256>>>(n);
    k_count <<<(E + 255) / 256, 256>>>(ei, E, n);
    k_dinv  <<<(n + 255) / 256, 256>>>(n);
    k_scan  <<<1, 1024>>>(n);
    k_fill  <<<(E + 255) / 256, 256>>>(ei, E, n);

    dim3 gt256(2, (n + 127) / 128);   // tensor GEMM, Nc=256
    dim3 gt64 (1, (n + 127) / 128);   // tensor GEMM, Nc=64
    dim3 gmed (1, (n + 127) / 128);   // SIMT small GEMMs

    // --- layer 1: GCN(256->256) + BN + leaky + residual ---
    k_gemm_tf32<<<gt256, 256, 65536>>>(x, W1, nullptr, pA, n, 256, 256);
    k_gemm_tf32<<<gt256, 256, 65536>>>(x, r1W, r1b, pB, n, 256, 256);
    k_gcn_gather256<<<(n * 32 + 255) / 256, 256>>>(pA, b1, pC, n);
    k_bnstats<256><<<512, 256>>>(pC, ps1, pq1, n);
    k_bnfin<256><<<1, 256>>>(ps1, pq1, g1, be1, n);
    k_apply<256><<<(n * 64 + 255) / 256, 256>>>(pC, pB, pC, n);   // x2 in pC

    // --- layer 2: GAT(256->64, 4 heads, mean) + BN + leaky + residual ---
    k_gemm_tf32<<<gt256, 256, 65536>>>(pC, Wg, nullptr, pA, n, 256, 256);
    k_gemm_tf32<<<gt64, 256, 65536>>>(pC, r2W, r2b, p64B, n, 256, 64);
    k_al <<<(n * 32 + 255) / 256, 256>>>(pA, a_src, a_dst, n);
    k_gat<<<(n * 32 + 255) / 256, 256>>>(pA, bg, p64A, n);
    k_bnstats<64><<<512, 256>>>(p64A, ps2, pq2, n);
    k_bnfin<64><<<1, 64>>>(ps2, pq2, g2, be2, n);
    k_apply<64><<<(n * 16 + 255) / 256, 256>>>(p64A, p64B, p64C, n);  // x3

    // --- layer 3: GCN(64->16) + BN + leaky + residual ---
    k_gemm<<<gmed, 256>>>(p64C, W3, nullptr, p16A, n, 64, 16);
    k_gcn_gather<16><<<(n * 4 + 255) / 256, 256>>>(p16A, b3, p16B, n);
    k_gemm<<<gmed, 256>>>(p64C, r3W, r3b, p16C, n, 64, 16);
    k_bnstats<16><<<512, 256>>>(p16B, ps3, pq3, n);
    k_bnfin<16><<<1, 16>>>(ps3, pq3, g3, be3, n);
    k_apply<16><<<(n * 4 + 255) / 256, 256>>>(p16B, p16C, p16A, n);   // x4

    // --- layer 4: GCN(16->64), then final projection ---
    k_gemm<<<gmed, 256>>>(p16A, W4, nullptr, p64A, n, 16, 64);
    k_gcn_gather<64><<<(n * 16 + 255) / 256, 256>>>(p64A, b4, p64B, n);
    k_gemm<<<gmed, 256>>>(p64B, pW, pb, outp, n, 64, 64);
}

// round 5
// speedup vs baseline: 2.3470x; 2.3470x over previous
#include <cuda_runtime.h>
#include <cuda_bf16.h>
#include <cstddef>
#include <cstdint>

// ---------------------------------------------------------------------------
// Problem constants
// ---------------------------------------------------------------------------
#define NN 50000
#define EE 800000
#define NTILES_MAX 391          // ceil(50048/128)

// ---------------------------------------------------------------------------
// Device-global scratch
// ---------------------------------------------------------------------------
__device__ float g_bufA[(size_t)NN * 256];
__device__ float g_bufB[(size_t)NN * 256];
__device__ float g_bufC[(size_t)NN * 256];
__device__ float g_b64A[(size_t)NN * 64];
__device__ float g_b64B[(size_t)NN * 64];
__device__ float g_b64C[(size_t)NN * 64];
__device__ float g_b16A[(size_t)NN * 16];
__device__ float g_b16B[(size_t)NN * 16];
__device__ float g_b16C[(size_t)NN * 16];
__device__ float g_als[(size_t)NN * 4];
__device__ float g_ald[(size_t)NN * 4];
__device__ float g_dinv[NN];
__device__ int   g_deg[NN];
__device__ int   g_cur[NN];
__device__ int   g_rowptr[NN + 1];
__device__ int   g_csr[EE];
__device__ float g_s1[256], g_q1[256];
__device__ float g_s2[64],  g_q2[64];
__device__ float g_s3[16],  g_q3[16];
__device__ float g_scale[256], g_shift[256];
__device__ int   g_is64;

// bf16 hi/lo "fragment image" buffers
// A image: [tile][chunk(8)][2048 words] per plane -> NTILES_MAX*8*512 uint4
__device__ uint4 g_iAh[(size_t)NTILES_MAX * 8 * 512];
__device__ uint4 g_iAl[(size_t)NTILES_MAX * 8 * 512];
// weight images: [ctile(<=2)][chunk(8)][2048 words] -> 2*8*512 = 8192 uint4
__device__ uint4 g_iW1h[8192], g_iW1l[8192];
__device__ uint4 g_iR1h[8192], g_iR1l[8192];
__device__ uint4 g_iWgh[8192], g_iWgl[8192];
__device__ uint4 g_iR2h[8192], g_iR2l[8192];

__device__ __forceinline__ float lk01(float x) { return x > 0.f ? x : 0.01f * x; }
__device__ __forceinline__ float lk2 (float x) { return x > 0.f ? x : 0.2f  * x; }

// ---------------------------------------------------------------------------
// Edge dtype detection (int64 vs int32 delivery)
// ---------------------------------------------------------------------------
__global__ void k_detect(const int* __restrict__ ei32, int E) {
    __shared__ int acc[32];
    int t = threadIdx.x;
    int o = 0;
    for (int i = 0; i < 8; i++) {
        int idx = 2 * (t + i * 32) + 1;
        if (idx < 2 * E) o |= ei32[idx];
    }
    acc[t] = o;
    __syncthreads();
    if (t == 0) {
        int r = 0;
        for (int i = 0; i < 32; i++) r |= acc[i];
        g_is64 = (r == 0) ? 1 : 0;
    }
}

__device__ __forceinline__ int edge_src(const void* ei, int E, int e) {
    if (g_is64) return (int)((const long long*)ei)[e];
    return ((const int*)ei)[e];
}
__device__ __forceinline__ int edge_dst(const void* ei, int E, int e) {
    if (g_is64) return (int)((const long long*)ei)[(size_t)E + e];
    return ((const int*)ei)[(size_t)E + e];
}

// ---------------------------------------------------------------------------
// Graph preprocessing
// ---------------------------------------------------------------------------
__global__ void k_zero(int n) {
    int i = blockIdx.x * blockDim.x + threadIdx.x;
    if (i < n)   { g_deg[i] = 0; g_cur[i] = 0; }
    if (i < 256) { g_s1[i] = 0.f; g_q1[i] = 0.f; }
    if (i < 64)  { g_s2[i] = 0.f; g_q2[i] = 0.f; }
    if (i < 16)  { g_s3[i] = 0.f; g_q3[i] = 0.f; }
}

__global__ void k_count(const void* __restrict__ ei, int E, int n) {
    int e = blockIdx.x * blockDim.x + threadIdx.x;
    if (e >= E) return;
    int d = edge_dst(ei, E, e);
    if ((unsigned)d < (unsigned)n) atomicAdd(&g_deg[d], 1);
}

__global__ void k_dinv(int n) {
    int i = blockIdx.x * blockDim.x + threadIdx.x;
    if (i < n) g_dinv[i] = rsqrtf((float)g_deg[i] + 1.0f);
}

__global__ void k_scan(int n) {
    __shared__ int sh[1024];
    int t = threadIdx.x;
    int chunk = (n + 1023) / 1024;
    int b = t * chunk;
    int e = b + chunk; if (e > n) e = n;
    int sum = 0;
    for (int i = b; i < e; i++) sum += g_deg[i];
    sh[t] = sum;
    __syncthreads();
    for (int off = 1; off < 1024; off <<= 1) {
        int v = (t >= off) ? sh[t - off] : 0;
        __syncthreads();
        sh[t] += v;
        __syncthreads();
    }
    int excl = (t == 0) ? 0 : sh[t - 1];
    for (int i = b; i < e; i++) { g_rowptr[i] = excl; excl += g_deg[i]; }
    if (t == 1023) g_rowptr[n] = sh[1023];
}

__global__ void k_fill(const void* __restrict__ ei, int E, int n) {
    int e = blockIdx.x * blockDim.x + threadIdx.x;
    if (e >= E) return;
    int src = edge_src(ei, E, e);
    int dst = edge_dst(ei, E, e);
    if ((unsigned)src >= (unsigned)n || (unsigned)dst >= (unsigned)n) return;
    int pos = g_rowptr[dst] + atomicAdd(&g_cur[dst], 1);
    if ((unsigned)pos < (unsigned)EE) g_csr[pos] = src;
}

// ---------------------------------------------------------------------------
// bf16 hi/lo split into fragment-image layout.
//
// m16n8k16 fragment maps (row.col):
//  A elem (r,k): reg = (r%16>=8) + 2*(k%16>=8), lane = (r%8)*4 + (k%8)/2,
//                halfslot = k&1  (low half = even k)
//  B elem (k,n): reg = (k%16>=8), lane = (n%8)*4 + (k%8)/2, halfslot = k&1
// A image word index: ((tile*8+chunk)*2048) + ((kt*8+mt8)*4+reg)*32 + lane
// B image word index: ((ctile*8+chunk)*2048) + ((kt*16+nt16)*2+reg)*32 + lane
// ---------------------------------------------------------------------------
__device__ __forceinline__ void bsplit(float v, uint32_t& h, uint32_t& l) {
    __nv_bfloat16 hb = __float2bfloat16(v);
    __nv_bfloat16 lb = __float2bfloat16(v - __bfloat162float(hb));
    h = (uint32_t)__bfloat16_as_ushort(hb);
    l = (uint32_t)__bfloat16_as_ushort(lb);
}

// A split: one uint4 (8 consecutive k) per plane per thread. K = 256 fixed.
__global__ void k_splitA(const float* __restrict__ src, uint4* __restrict__ ih,
                         uint4* __restrict__ il, int M, int ntiles)
{
    int task = blockIdx.x * blockDim.x + threadIdx.x;
    int total = ntiles * 128 * 32;
    if (task >= total) return;
    int r = task >> 5, k0 = (task & 31) * 8;
    float v[8];
    if (r < M) {
        const float4* p = (const float4*)(src + (size_t)r * 256 + k0);
        float4 f0 = p[0], f1 = p[1];
        v[0] = f0.x; v[1] = f0.y; v[2] = f0.z; v[3] = f0.w;
        v[4] = f1.x; v[5] = f1.y; v[6] = f1.z; v[7] = f1.w;
    } else {
#pragma unroll
        for (int j = 0; j < 8; j++) v[j] = 0.f;
    }
    uint32_t hw[4], lw[4];
#pragma unroll
    for (int j = 0; j < 4; j++) {
        uint32_t h0, l0, h1, l1;
        bsplit(v[2 * j], h0, l0);
        bsplit(v[2 * j + 1], h1, l1);
        hw[j] = h0 | (h1 << 16);
        lw[j] = l0 | (l1 << 16);
    }
    int tile = r >> 7, rr = r & 127;
    int chunk = k0 >> 5;
    int kt = (k0 >> 4) & 1;
    int mt8 = rr >> 4;
    int reg = (((rr & 15) >= 8) ? 1 : 0) + (((k0 & 15) >= 8) ? 2 : 0);
    int u4 = (tile * 8 + chunk) * 512 + ((kt * 8 + mt8) * 4 + reg) * 8 + (rr & 7);
    ih[u4] = make_uint4(hw[0], hw[1], hw[2], hw[3]);
    il[u4] = make_uint4(lw[0], lw[1], lw[2], lw[3]);
}

// B split: one packed word per thread. B is [K=256, Nc] row-major.
__global__ void k_splitB(const float* __restrict__ B, uint32_t* __restrict__ ih,
                         uint32_t* __restrict__ il, int Nc, int nct)
{
    int idx = blockIdx.x * blockDim.x + threadIdx.x;
    int total = nct * 8 * 2048;
    if (idx >= total) return;
    int ctile = idx / (8 * 2048);
    int rem0 = idx % (8 * 2048);
    int chunk = rem0 >> 11;
    int rem = rem0 & 2047;
    int lane = rem & 31;
    int t2 = rem >> 5;
    int reg = t2 & 1;
    int t3 = t2 >> 1;
    int nt16 = t3 & 15;
    int kt = t3 >> 4;
    int n = ctile * 128 + nt16 * 8 + (lane >> 2);
    int k = chunk * 32 + kt * 16 + reg * 8 + (lane & 3) * 2;
    float v0 = (n < Nc) ? B[(size_t)k * Nc + n] : 0.f;
    float v1 = (n < Nc) ? B[(size_t)(k + 1) * Nc + n] : 0.f;
    uint32_t h0, l0, h1, l1;
    bsplit(v0, h0, l0);
    bsplit(v1, h1, l1);
    ih[idx] = h0 | (h1 << 16);
    il[idx] = l0 | (l1 << 16);
}

// ---------------------------------------------------------------------------
// bf16 3-term tensor GEMM from fragment images. K=256 (8 chunks of 32).
// C[M,Nc] = A@B (+bias). Tile 128x128, 256 threads, cp.async double buffer.
// ---------------------------------------------------------------------------
__device__ __forceinline__ void mma_bf16(float* c, const uint32_t* a, const uint32_t* b) {
    asm volatile(
        "mma.sync.aligned.m16n8k16.row.col.f32.bf16.bf16.f32 "
        "{%0,%1,%2,%3}, {%4,%5,%6,%7}, {%8,%9}, {%0,%1,%2,%3};"
        : "+f"(c[0]), "+f"(c[1]), "+f"(c[2]), "+f"(c[3])
        : "r"(a[0]), "r"(a[1]), "r"(a[2]), "r"(a[3]), "r"(b[0]), "r"(b[1]));
}

__global__ void __launch_bounds__(256) k_gemm_bf16(
    const uint4* __restrict__ iAh, const uint4* __restrict__ iAl,
    const uint4* __restrict__ iBh, const uint4* __restrict__ iBl,
    const float* __restrict__ bias, float* __restrict__ C,
    int M, int Nc)
{
    extern __shared__ uint32_t smem[];   // [2 buf][4 planes][2048 words] = 64KB
    uint32_t sbase;
    asm("{ .reg .u64 t; cvta.to.shared.u64 t, %1; cvt.u32.u64 %0, t; }"
        : "=r"(sbase) : "l"(smem));

    int tid = threadIdx.x, lane = tid & 31, warp = tid >> 5;
    int wm = warp >> 2, wn = warp & 3;
    int tile = blockIdx.y, ctile = blockIdx.x;

    float acc[4][4][4];
#pragma unroll
    for (int mt = 0; mt < 4; mt++)
#pragma unroll
        for (int nt = 0; nt < 4; nt++)
#pragma unroll
            for (int r = 0; r < 4; r++) acc[mt][nt][r] = 0.f;

    auto issue = [&](int ch, int buf) {
        const uint4* s0 = iAh + (size_t)(tile * 8 + ch) * 512;
        const uint4* s1 = iAl + (size_t)(tile * 8 + ch) * 512;
        const uint4* s2 = iBh + (size_t)(ctile * 8 + ch) * 512;
        const uint4* s3 = iBl + (size_t)(ctile * 8 + ch) * 512;
        uint32_t d = sbase + buf * 32768;
#pragma unroll
        for (int i = 0; i < 2; i++) {
            int j = tid + i * 256;
            asm volatile("cp.async.cg.shared.global [%0], [%1], 16;\n"
                         :: "r"(d + j * 16), "l"(s0 + j));
            asm volatile("cp.async.cg.shared.global [%0], [%1], 16;\n"
                         :: "r"(d + 8192 + j * 16), "l"(s1 + j));
            asm volatile("cp.async.cg.shared.global [%0], [%1], 16;\n"
                         :: "r"(d + 16384 + j * 16), "l"(s2 + j));
            asm volatile("cp.async.cg.shared.global [%0], [%1], 16;\n"
                         :: "r"(d + 24576 + j * 16), "l"(s3 + j));
        }
        asm volatile("cp.async.commit_group;\n" ::: "memory");
    };

    issue(0, 0);

    for (int ch = 0; ch < 8; ch++) {
        if (ch + 1 < 8) {
            issue(ch + 1, (ch + 1) & 1);
            asm volatile("cp.async.wait_group 1;\n" ::: "memory");
        } else {
            asm volatile("cp.async.wait_group 0;\n" ::: "memory");
        }
        __syncthreads();

        const uint32_t* Ah = smem + (ch & 1) * 8192;
        const uint32_t* Al = Ah + 2048;
        const uint32_t* Bh = Ah + 4096;
        const uint32_t* Bl = Ah + 6144;

#pragma unroll
        for (int kt = 0; kt < 2; kt++) {
            uint32_t bh[4][2], bl[4][2];
#pragma unroll
            for (int nt = 0; nt < 4; nt++) {
                int base = ((kt * 16 + wn * 4 + nt) * 2) * 32 + lane;
                bh[nt][0] = Bh[base];      bh[nt][1] = Bh[base + 32];
                bl[nt][0] = Bl[base];      bl[nt][1] = Bl[base + 32];
            }
#pragma unroll
            for (int mt = 0; mt < 4; mt++) {
                uint32_t ah[4], al[4];
                int ab = ((kt * 8 + wm * 4 + mt) * 4) * 32 + lane;
                ah[0] = Ah[ab];       ah[1] = Ah[ab + 32];
                ah[2] = Ah[ab + 64];  ah[3] = Ah[ab + 96];
                al[0] = Al[ab];       al[1] = Al[ab + 32];
                al[2] = Al[ab + 64];  al[3] = Al[ab + 96];
#pragma unroll
                for (int nt = 0; nt < 4; nt++) {
                    mma_bf16(acc[mt][nt], ah, bh[nt]);
                    mma_bf16(acc[mt][nt], al, bh[nt]);
                    mma_bf16(acc[mt][nt], ah, bl[nt]);
                }
            }
        }
        __syncthreads();
    }

    // epilogue
    int row0 = tile * 128, col0 = ctile * 128;
    int gid = lane >> 2, tig = lane & 3;
#pragma unroll
    for (int mt = 0; mt < 4; mt++) {
#pragma unroll
        for (int nt = 0; nt < 4; nt++) {
            int col = col0 + wn * 32 + nt * 8 + tig * 2;
            if (col < Nc) {
                float b0 = bias ? bias[col] : 0.f;
                float b1 = bias ? bias[col + 1] : 0.f;
                int r1 = row0 + wm * 64 + mt * 16 + gid;
                if (r1 < M) {
                    float2 o = make_float2(acc[mt][nt][0] + b0, acc[mt][nt][1] + b1);
                    *(float2*)(C + (size_t)r1 * Nc + col) = o;
                }
                int r2 = r1 + 8;
                if (r2 < M) {
                    float2 o = make_float2(acc[mt][nt][2] + b0, acc[mt][nt][3] + b1);
                    *(float2*)(C + (size_t)r2 * Nc + col) = o;
                }
            }
        }
    }
}

// ---------------------------------------------------------------------------
// SIMT SGEMM (small layer-3/4 GEMMs). 128x128 tile, 8x8 micro, BK=8.
// ---------------------------------------------------------------------------
__global__ void __launch_bounds__(256) k_gemm(
    const float* __restrict__ A, const float* __restrict__ B,
    const float* __restrict__ bias, float* __restrict__ C,
    int M, int K, int Nc)
{
    __shared__ float As[8][132];
    __shared__ float Bs[8][128];
    int tid = threadIdx.x;
    int tx = tid & 15, ty = tid >> 4;
    int row0 = blockIdx.y * 128, col0 = blockIdx.x * 128;

    int arow = tid >> 1;
    int ak   = (tid & 1) * 4;
    int brow = tid >> 5;
    int bc   = (tid & 31) * 4;

    bool aok = (row0 + arow) < M;
    bool bok = (col0 + bc + 3) < Nc;

    float acc[8][8];
#pragma unroll
    for (int i = 0; i < 8; i++)
#pragma unroll
        for (int j = 0; j < 8; j++) acc[i][j] = 0.f;

    for (int k0 = 0; k0 < K; k0 += 8) {
        float4 av = make_float4(0.f, 0.f, 0.f, 0.f);
        if (aok) av = *(const float4*)(A + (size_t)(row0 + arow) * K + k0 + ak);
        As[ak + 0][arow] = av.x;
        As[ak + 1][arow] = av.y;
        As[ak + 2][arow] = av.z;
        As[ak + 3][arow] = av.w;
        float4 bv = make_float4(0.f, 0.f, 0.f, 0.f);
        if (bok) bv = *(const float4*)(B + (size_t)(k0 + brow) * Nc + col0 + bc);
        *(float4*)&Bs[brow][bc] = bv;
        __syncthreads();
#pragma unroll
        for (int k = 0; k < 8; k++) {
            float4 a0 = *(const float4*)&As[k][ty * 8];
            float4 a1 = *(const float4*)&As[k][ty * 8 + 4];
            float4 b0 = *(const float4*)&Bs[k][tx * 8];
            float4 b1 = *(const float4*)&Bs[k][tx * 8 + 4];
            float a[8] = {a0.x, a0.y, a0.z, a0.w, a1.x, a1.y, a1.z, a1.w};
            float b[8] = {b0.x, b0.y, b0.z, b0.w, b1.x, b1.y, b1.z, b1.w};
#pragma unroll
            for (int i = 0; i < 8; i++)
#pragma unroll
                for (int j = 0; j < 8; j++) acc[i][j] += a[i] * b[j];
        }
        __syncthreads();
    }

    bool cok = (col0 + tx * 8 + 7) < Nc;
    float bvv[8];
#pragma unroll
    for (int j = 0; j < 8; j++)
        bvv[j] = (bias && cok) ? bias[col0 + tx * 8 + j] : 0.f;

    if (cok) {
#pragma unroll
        for (int i = 0; i < 8; i++) {
            int r = row0 + ty * 8 + i;
            if (r < M) {
                float* cp = C + (size_t)r * Nc + col0 + tx * 8;
                float4 o0 = make_float4(acc[i][0] + bvv[0], acc[i][1] + bvv[1],
                                        acc[i][2] + bvv[2], acc[i][3] + bvv[3]);
                float4 o1 = make_float4(acc[i][4] + bvv[4], acc[i][5] + bvv[5],
                                        acc[i][6] + bvv[6], acc[i][7] + bvv[7]);
                *(float4*)cp = o0;
                *(float4*)(cp + 4) = o1;
            }
        }
    }
}

// ---------------------------------------------------------------------------
// GCN gather kernels
// ---------------------------------------------------------------------------
__global__ void k_gcn_gather256(const float* __restrict__ h, const float* __restrict__ bias,
                                float* __restrict__ out, int n)
{
    int gt = blockIdx.x * blockDim.x + threadIdx.x;
    int nd = gt >> 5, lane = gt & 31;
    if (nd >= n) return;
    int f0 = lane * 8;
    float din = g_dinv[nd];
    float sw = din * din;
    const float4* hp = (const float4*)(h + (size_t)nd * 256 + f0);
    float4 v0 = hp[0], v1 = hp[1];
    const float4* bp = (const float4*)(bias + f0);
    float4 b0 = bp[0], b1 = bp[1];
    float4 a0, a1;
    a0.x = v0.x * sw + b0.x; a0.y = v0.y * sw + b0.y;
    a0.z = v0.z * sw + b0.z; a0.w = v0.w * sw + b0.w;
    a1.x = v1.x * sw + b1.x; a1.y = v1.y * sw + b1.y;
    a1.z = v1.z * sw + b1.z; a1.w = v1.w * sw + b1.w;
    int e = g_rowptr[nd], end = g_rowptr[nd + 1];
    for (; e < end; e++) {
        int s = g_csr[e];
        float wg = g_dinv[s] * din;
        const float4* sp = (const float4*)(h + (size_t)s * 256 + f0);
        float4 u0 = sp[0], u1 = sp[1];
        a0.x += wg * u0.x; a0.y += wg * u0.y; a0.z += wg * u0.z; a0.w += wg * u0.w;
        a1.x += wg * u1.x; a1.y += wg * u1.y; a1.z += wg * u1.z; a1.w += wg * u1.w;
    }
    float4* op = (float4*)(out + (size_t)nd * 256 + f0);
    op[0] = a0; op[1] = a1;
}

template <int C>
__global__ void k_gcn_gather(const float* __restrict__ h, const float* __restrict__ bias,
                             float* __restrict__ out, int n)
{
    const int G = C / 4;
    int gt = blockIdx.x * blockDim.x + threadIdx.x;
    int nd = gt / G, sub = gt % G;
    if (nd >= n) return;
    int f0 = sub * 4;
    float din = g_dinv[nd];
    float sw = din * din;
    float4 v = *(const float4*)(h + (size_t)nd * C + f0);
    float4 b = *(const float4*)(bias + f0);
    float4 a;
    a.x = v.x * sw + b.x; a.y = v.y * sw + b.y;
    a.z = v.z * sw + b.z; a.w = v.w * sw + b.w;
    int e = g_rowptr[nd], end = g_rowptr[nd + 1];
    for (; e < end; e++) {
        int s = g_csr[e];
        float wg = g_dinv[s] * din;
        float4 u = *(const float4*)(h + (size_t)s * C + f0);
        a.x += wg * u.x; a.y += wg * u.y; a.z += wg * u.z; a.w += wg * u.w;
    }
    *(float4*)(out + (size_t)nd * C + f0) = a;
}

// ---------------------------------------------------------------------------
// GAT kernels
// ---------------------------------------------------------------------------
__global__ void k_al(const float* __restrict__ hg, const float* __restrict__ a_s,
                     const float* __restrict__ a_d, int n)
{
    int gt = blockIdx.x * blockDim.x + threadIdx.x;
    int w = gt >> 5, lane = gt & 31;
    if (w >= n) return;
    float s0 = 0.f, s1 = 0.f, s2 = 0.f, s3 = 0.f;
    float d0 = 0.f, d1 = 0.f, d2 = 0.f, d3 = 0.f;
#pragma unroll
    for (int j = 0; j < 2; j++) {
        int f = lane * 4 + j * 128;
        float4 v  = *(const float4*)(hg + (size_t)w * 256 + f);
        float4 as = *(const float4*)(a_s + f);
        float4 ad = *(const float4*)(a_d + f);
        float ps = v.x * as.x + v.y * as.y + v.z * as.z + v.w * as.w;
        float pd = v.x * ad.x + v.y * ad.y + v.z * ad.z + v.w * ad.w;
        bool hi = (lane & 16) != 0;
        if (j == 0) { if (hi) { s1 += ps; d1 += pd; } else { s0 += ps; d0 += pd; } }
        else        { if (hi) { s3 += ps; d3 += pd; } else { s2 += ps; d2 += pd; } }
    }
#pragma unroll
    for (int off = 16; off >= 1; off >>= 1) {
        s0 += __shfl_xor_sync(0xffffffffu, s0, off);
        s1 += __shfl_xor_sync(0xffffffffu, s1, off);
        s2 += __shfl_xor_sync(0xffffffffu, s2, off);
        s3 += __shfl_xor_sync(0xffffffffu, s3, off);
        d0 += __shfl_xor_sync(0xffffffffu, d0, off);
        d1 += __shfl_xor_sync(0xffffffffu, d1, off);
        d2 += __shfl_xor_sync(0xffffffffu, d2, off);
        d3 += __shfl_xor_sync(0xffffffffu, d3, off);
    }
    if (lane == 0) {
        *(float4*)(g_als + 4 * (size_t)w) = make_float4(s0, s1, s2, s3);
        *(float4*)(g_ald + 4 * (size_t)w) = make_float4(d0, d1, d2, d3);
    }
}

__global__ void k_gat(const float* __restrict__ hg, const float* __restrict__ bg,
                      float* __restrict__ out, int n)
{
    int gt = blockIdx.x * blockDim.x + threadIdx.x;
    int w = gt >> 5, lane = gt & 31;
    if (w >= n) return;
    float4 ad = *(const float4*)(g_ald + 4 * (size_t)w);
    float4 sf = *(const float4*)(g_als + 4 * (size_t)w);
    float e0 = lk2(sf.x + ad.x), e1 = lk2(sf.y + ad.y);
    float e2 = lk2(sf.z + ad.z), e3 = lk2(sf.w + ad.w);
    float m0 = e0, m1 = e1, m2 = e2, m3 = e3;
    int beg = g_rowptr[w], end = g_rowptr[w + 1];
    for (int e = beg; e < end; e++) {
        int s = g_csr[e];
        float4 a = *(const float4*)(g_als + 4 * (size_t)s);
        m0 = fmaxf(m0, lk2(a.x + ad.x));
        m1 = fmaxf(m1, lk2(a.y + ad.y));
        m2 = fmaxf(m2, lk2(a.z + ad.z));
        m3 = fmaxf(m3, lk2(a.w + ad.w));
    }
    float den0 = __expf(e0 - m0), den1 = __expf(e1 - m1);
    float den2 = __expf(e2 - m2), den3 = __expf(e3 - m3);
    int f0 = lane * 8;
    int head = lane >> 3;
    float wself = head == 0 ? den0 : head == 1 ? den1 : head == 2 ? den2 : den3;
    const float4* hp = (const float4*)(hg + (size_t)w * 256 + f0);
    float4 v0 = hp[0], v1 = hp[1];
    float a0 = wself * v0.x, a1 = wself * v0.y, a2 = wself * v0.z, a3 = wself * v0.w;
    float a4 = wself * v1.x, a5 = wself * v1.y, a6 = wself * v1.z, a7 = wself * v1.w;
    for (int e = beg; e < end; e++) {
        int s = g_csr[e];
        float4 a = *(const float4*)(g_als + 4 * (size_t)s);
        float w0 = __expf(lk2(a.x + ad.x) - m0);
        float w1 = __expf(lk2(a.y + ad.y) - m1);
        float w2 = __expf(lk2(a.z + ad.z) - m2);
        float w3 = __expf(lk2(a.w + ad.w) - m3);
        den0 += w0; den1 += w1; den2 += w2; den3 += w3;
        float ws = head == 0 ? w0 : head == 1 ? w1 : head == 2 ? w2 : w3;
        const float4* sp = (const float4*)(hg + (size_t)s * 256 + f0);
        float4 u0 = sp[0], u1 = sp[1];
        a0 += ws * u0.x; a1 += ws * u0.y; a2 += ws * u0.z; a3 += ws * u0.w;
        a4 += ws * u1.x; a5 += ws * u1.y; a6 += ws * u1.z; a7 += ws * u1.w;
    }
    float dsel = head == 0 ? den0 : head == 1 ? den1 : head == 2 ? den2 : den3;
    float sc = 0.25f / dsel;
    a0 *= sc; a1 *= sc; a2 *= sc; a3 *= sc;
    a4 *= sc; a5 *= sc; a6 *= sc; a7 *= sc;
    a0 += __shfl_xor_sync(0xffffffffu, a0, 8);  a0 += __shfl_xor_sync(0xffffffffu, a0, 16);
    a1 += __shfl_xor_sync(0xffffffffu, a1, 8);  a1 += __shfl_xor_sync(0xffffffffu, a1, 16);
    a2 += __shfl_xor_sync(0xffffffffu, a2, 8);  a2 += __shfl_xor_sync(0xffffffffu, a2, 16);
    a3 += __shfl_xor_sync(0xffffffffu, a3, 8);  a3 += __shfl_xor_sync(0xffffffffu, a3, 16);
    a4 += __shfl_xor_sync(0xffffffffu, a4, 8);  a4 += __shfl_xor_sync(0xffffffffu, a4, 16);
    a5 += __shfl_xor_sync(0xffffffffu, a5, 8);  a5 += __shfl_xor_sync(0xffffffffu, a5, 16);
    a6 += __shfl_xor_sync(0xffffffffu, a6, 8);  a6 += __shfl_xor_sync(0xffffffffu, a6, 16);
    a7 += __shfl_xor_sync(0xffffffffu, a7, 8);  a7 += __shfl_xor_sync(0xffffffffu, a7, 16);
    if (lane < 8) {
        const float4* bp = (const float4*)(bg + lane * 8);
        float4 b0 = bp[0], b1 = bp[1];
        float4 o0 = make_float4(a0 + b0.x, a1 + b0.y, a2 + b0.z, a3 + b0.w);
        float4 o1 = make_float4(a4 + b1.x, a5 + b1.y, a6 + b1.z, a7 + b1.w);
        float4* op = (float4*)(out + (size_t)w * 64 + lane * 8);
        op[0] = o0; op[1] = o1;
    }
}

// ---------------------------------------------------------------------------
// BatchNorm: stats / finalize / apply(+leaky+residual)
// ---------------------------------------------------------------------------
template <int C>
__global__ void k_bnstats(const float* __restrict__ x, float* __restrict__ gsum,
                          float* __restrict__ gsq, int n)
{
    __shared__ float ss[256], qq[256];
    int tid = threadIdx.x;
    const int R = 256 / C;
    int c = tid % C, r0 = tid / C;
    float s = 0.f, q = 0.f;
    for (int r = blockIdx.x * R + r0; r < n; r += gridDim.x * R) {
        float v = x[(size_t)r * C + c];
        s += v; q += v * v;
    }
    ss[tid] = s; qq[tid] = q;
    __syncthreads();
#pragma unroll
    for (int off = 128; off >= C; off >>= 1) {
        if (tid < off) { ss[tid] += ss[tid + off]; qq[tid] += qq[tid + off]; }
        __syncthreads();
    }
    if (tid < C) {
        atomicAdd(&gsum[tid], ss[tid]);
        atomicAdd(&gsq[tid],  qq[tid]);
    }
}

template <int C>
__global__ void k_bnfin(const float* __restrict__ gsum, const float* __restrict__ gsq,
                        const float* __restrict__ g, const float* __restrict__ be, int n)
{
    int c = threadIdx.x;
    if (c >= C) return;
    float inv = 1.0f / (float)n;
    float mu = gsum[c] * inv;
    float var = gsq[c] * inv - mu * mu;
    float sc = g[c] * rsqrtf(var + 1e-5f);
    g_scale[c] = sc;
    g_shift[c] = be[c] - mu * sc;
}

template <int C>
__global__ void k_apply(const float* __restrict__ x, const float* __restrict__ res,
                        float* __restrict__ out, int n)
{
    int i = blockIdx.x * blockDim.x + threadIdx.x;
    int total = n * (C / 4);
    if (i >= total) return;
    int c4 = i % (C / 4);
    float4 sc = *(const float4*)(g_scale + c4 * 4);
    float4 sh = *(const float4*)(g_shift + c4 * 4);
    float4 v = ((const float4*)x)[i];
    float4 r = ((const float4*)res)[i];
    float4 o;
    o.x = lk01(v.x * sc.x + sh.x) + r.x;
    o.y = lk01(v.y * sc.y + sh.y) + r.y;
    o.z = lk01(v.z * sc.z + sh.z) + r.z;
    o.w = lk01(v.w * sc.w + sh.w) + r.w;
    ((float4*)out)[i] = o;
}

// ---------------------------------------------------------------------------
// Launcher
// ---------------------------------------------------------------------------
extern "C" void kernel_launch(void* const* d_in, const int* in_sizes, int n_in,
                              void* d_out, int out_size)
{
    const float* x     = (const float*)d_in[0];
    const void*  ei    = d_in[1];
    const float* W1    = (const float*)d_in[2];
    const float* b1    = (const float*)d_in[3];
    const float* g1    = (const float*)d_in[4];
    const float* be1   = (const float*)d_in[5];
    const float* Wg    = (const float*)d_in[6];
    const float* a_src = (const float*)d_in[7];
    const float* a_dst = (const float*)d_in[8];
    const float* bg    = (const float*)d_in[9];
    const float* g2    = (const float*)d_in[10];
    const float* be2   = (const float*)d_in[11];
    const float* W3    = (const float*)d_in[12];
    const float* b3    = (const float*)d_in[13];
    const float* g3    = (const float*)d_in[14];
    const float* be3   = (const float*)d_in[15];
    const float* W4    = (const float*)d_in[16];
    const float* b4    = (const float*)d_in[17];
    const float* r1W   = (const float*)d_in[18];
    const float* r1b   = (const float*)d_in[19];
    const float* r2W   = (const float*)d_in[20];
    const float* r2b   = (const float*)d_in[21];
    const float* r3W   = (const float*)d_in[22];
    const float* r3b   = (const float*)d_in[23];
    const float* pW    = (const float*)d_in[24];
    const float* pb    = (const float*)d_in[25];

    int n = in_sizes[0] / 256;
    int E = in_sizes[1] / 2;
    if (E > EE) E = EE;
    int ntiles = (n + 127) / 128;
    if (ntiles > NTILES_MAX) ntiles = NTILES_MAX;

    float *pA, *pB, *pC, *p64A, *p64B, *p64C, *p16A, *p16B, *p16C;
    float *ps1, *pq1, *ps2, *pq2, *ps3, *pq3;
    uint4 *iAh, *iAl, *iW1h, *iW1l, *iR1h, *iR1l, *iWgh, *iWgl, *iR2h, *iR2l;
    cudaGetSymbolAddress((void**)&pA,   g_bufA);
    cudaGetSymbolAddress((void**)&pB,   g_bufB);
    cudaGetSymbolAddress((void**)&pC,   g_bufC);
    cudaGetSymbolAddress((void**)&p64A, g_b64A);
    cudaGetSymbolAddress((void**)&p64B, g_b64B);
    cudaGetSymbolAddress((void**)&p64C, g_b64C);
    cudaGetSymbolAddress((void**)&p16A, g_b16A);
    cudaGetSymbolAddress((void**)&p16B, g_b16B);
    cudaGetSymbolAddress((void**)&p16C, g_b16C);
    cudaGetSymbolAddress((void**)&ps1, g_s1);
    cudaGetSymbolAddress((void**)&pq1, g_q1);
    cudaGetSymbolAddress((void**)&ps2, g_s2);
    cudaGetSymbolAddress((void**)&pq2, g_q2);
    cudaGetSymbolAddress((void**)&ps3, g_s3);
    cudaGetSymbolAddress((void**)&pq3, g_q3);
    cudaGetSymbolAddress((void**)&iAh,  g_iAh);
    cudaGetSymbolAddress((void**)&iAl,  g_iAl);
    cudaGetSymbolAddress((void**)&iW1h, g_iW1h);
    cudaGetSymbolAddress((void**)&iW1l, g_iW1l);
    cudaGetSymbolAddress((void**)&iR1h, g_iR1h);
    cudaGetSymbolAddress((void**)&iR1l, g_iR1l);
    cudaGetSymbolAddress((void**)&iWgh, g_iWgh);
    cudaGetSymbolAddress((void**)&iWgl, g_iWgl);
    cudaGetSymbolAddress((void**)&iR2h, g_iR2h);
    cudaGetSymbolAddress((void**)&iR2l, g_iR2l);

    float* outp = (float*)d_out;

    cudaFuncSetAttribute(k_gemm_bf16, cudaFuncAttributeMaxDynamicSharedMemorySize, 65536);

    // --- graph preprocessing: CSR by dst ---
    k_detect<<<1, 32>>>((const int*)ei, E);
    k_zero  <<<(n + 255) / 256, 256>>>(n);
    k_count <<<(E + 255) / 256, 256>>>(ei, E, n);
    k_dinv  <<<(n + 255) / 256, 256>>>(n);
    k_scan  <<<1, 1024>>>(n);
    k_fill  <<<(E + 255) / 256, 256>>>(ei, E, n);

    int splitA_blocks = (ntiles * 128 * 32 + 255) / 256;
    dim3 gt256(2, ntiles);
    dim3 gt64 (1, ntiles);
    dim3 gmed (1, ntiles);

    // --- weight splits (tiny) ---
    k_splitB<<<128, 256>>>(W1,  (uint32_t*)iW1h, (uint32_t*)iW1l, 256, 2);
    k_splitB<<<128, 256>>>(r1W, (uint32_t*)iR1h, (uint32_t*)iR1l, 256, 2);
    k_splitB<<<128, 256>>>(Wg,  (uint32_t*)iWgh, (uint32_t*)iWgl, 256, 2);
    k_splitB<<<64,  256>>>(r2W, (uint32_t*)iR2h, (uint32_t*)iR2l, 64, 1);

    // --- layer 1: GCN(256->256) + BN + leaky + residual ---
    k_splitA<<<splitA_blocks, 256>>>(x, iAh, iAl, n, ntiles);
    k_gemm_bf16<<<gt256, 256, 65536>>>(iAh, iAl, iW1h, iW1l, nullptr, pA, n, 256);
    k_gemm_bf16<<<gt256, 256, 65536>>>(iAh, iAl, iR1h, iR1l, r1b, pB, n, 256);
    k_gcn_gather256<<<(n * 32 + 255) / 256, 256>>>(pA, b1, pC, n);
    k_bnstats<256><<<512, 256>>>(pC, ps1, pq1, n);
    k_bnfin<256><<<1, 256>>>(ps1, pq1, g1, be1, n);
    k_apply<256><<<(n * 64 + 255) / 256, 256>>>(pC, pB, pC, n);   // x2 in pC

    // --- layer 2: GAT(256->64, 4 heads, mean) + BN + leaky + residual ---
    k_splitA<<<splitA_blocks, 256>>>(pC, iAh, iAl, n, ntiles);
    k_gemm_bf16<<<gt256, 256, 65536>>>(iAh, iAl, iWgh, iWgl, nullptr, pA, n, 256);
    k_gemm_bf16<<<gt64, 256, 65536>>>(iAh, iAl, iR2h, iR2l, r2b, p64B, n, 64);
    k_al <<<(n * 32 + 255) / 256, 256>>>(pA, a_src, a_dst, n);
    k_gat<<<(n * 32 + 255) / 256, 256>>>(pA, bg, p64A, n);
    k_bnstats<64><<<512, 256>>>(p64A, ps2, pq2, n);
    k_bnfin<64><<<1, 64>>>(ps2, pq2, g2, be2, n);
    k_apply<64><<<(n * 16 + 255) / 256, 256>>>(p64A, p64B, p64C, n);  // x3

    // --- layer 3: GCN(64->16) + BN + leaky + residual ---
    k_gemm<<<gmed, 256>>>(p64C, W3, nullptr, p16A, n, 64, 16);
    k_gcn_gather<16><<<(n * 4 + 255) / 256, 256>>>(p16A, b3, p16B, n);
    k_gemm<<<gmed, 256>>>(p64C, r3W, r3b, p16C, n, 64, 16);
    k_bnstats<16><<<512, 256>>>(p16B, ps3, pq3, n);
    k_bnfin<16><<<1, 16>>>(ps3, pq3, g3, be3, n);
    k_apply<16><<<(n * 4 + 255) / 256, 256>>>(p16B, p16C, p16A, n);   // x4

    // --- layer 4: GCN(16->64), then final projection ---
    k_gemm<<<gmed, 256>>>(p16A, W4, nullptr, p64A, n, 16, 64);
    k_gcn_gather<64><<<(n * 16 + 255) / 256, 256>>>(p64A, b4, p64B, n);
    k_gemm<<<gmed, 256>>>(p64B, pW, pb, outp, n, 64, 64);
}